// round 5
// baseline (speedup 1.0000x reference)
#include <cuda_runtime.h>
#include <math.h>

#define NB   4
#define NTOK 65536
#define CD   256
#define LD   64
#define SD   64
#define AD   16
#define TT   64
#define BPB  37
#define NTILE 1024
#define PC 260
#define PL 68
#define PV 132

__device__ float g_w[(size_t)NB * NTOK * SD];
__device__ float g_slice[NB * SD * CD];
__device__ float g_wsum[NB * SD];
__device__ float g_st[NB * SD * CD];

__device__ __forceinline__ float geluf(float x) {
    return 0.5f * x * (1.0f + erff(x * 0.70710678118654752f));
}

// ---------- 512-thread micro-kernel: 2x4 outputs (rows tr,tr+32; cols tc*4..+3) ----------
__device__ __forceinline__ void mm2x4(const float* __restrict__ A, int ald,
                                      const float* __restrict__ B, int bld,
                                      int tr, int tc, float (&acc)[2][4])
{
#pragma unroll 8
    for (int kk = 0; kk < 64; kk++) {
        float4 b4 = *reinterpret_cast<const float4*>(B + kk * bld + tc * 4);
        float a0 = A[tr * ald + kk];
        float a1 = A[(tr + 32) * ald + kk];
        acc[0][0] = fmaf(a0, b4.x, acc[0][0]); acc[0][1] = fmaf(a0, b4.y, acc[0][1]);
        acc[0][2] = fmaf(a0, b4.z, acc[0][2]); acc[0][3] = fmaf(a0, b4.w, acc[0][3]);
        acc[1][0] = fmaf(a1, b4.x, acc[1][0]); acc[1][1] = fmaf(a1, b4.y, acc[1][1]);
        acc[1][2] = fmaf(a1, b4.z, acc[1][2]); acc[1][3] = fmaf(a1, b4.w, acc[1][3]);
    }
}

// A transposed variant: A[k][row], ld ald
__device__ __forceinline__ void mmT2x4(const float* __restrict__ A, int ald,
                                       const float* __restrict__ B, int bld,
                                       int tr, int tc, float (&acc)[2][4])
{
#pragma unroll 8
    for (int kk = 0; kk < 64; kk++) {
        float4 b4 = *reinterpret_cast<const float4*>(B + kk * bld + tc * 4);
        float a0 = A[kk * ald + tr];
        float a1 = A[kk * ald + tr + 32];
        acc[0][0] = fmaf(a0, b4.x, acc[0][0]); acc[0][1] = fmaf(a0, b4.y, acc[0][1]);
        acc[0][2] = fmaf(a0, b4.z, acc[0][2]); acc[0][3] = fmaf(a0, b4.w, acc[0][3]);
        acc[1][0] = fmaf(a1, b4.x, acc[1][0]); acc[1][1] = fmaf(a1, b4.y, acc[1][1]);
        acc[1][2] = fmaf(a1, b4.z, acc[1][2]); acc[1][3] = fmaf(a1, b4.w, acc[1][3]);
    }
}

// ---------- 256-thread 4x4 micro-kernel (k2 only) ----------
__device__ __forceinline__ void mm64q(const float* __restrict__ A, int ald,
                                      const float* __restrict__ B, int bld,
                                      int tr, int tc, float (&acc)[4][4])
{
#pragma unroll 8
    for (int kk = 0; kk < 64; kk++) {
        float4 b4 = *reinterpret_cast<const float4*>(B + kk * bld + tc * 4);
        float a[4] = { A[tr * ald + kk], A[(tr + 16) * ald + kk],
                       A[(tr + 32) * ald + kk], A[(tr + 48) * ald + kk] };
        float bb[4] = { b4.x, b4.y, b4.z, b4.w };
#pragma unroll
        for (int i = 0; i < 4; i++)
#pragma unroll
            for (int j = 0; j < 4; j++) acc[i][j] = fmaf(a[i], bb[j], acc[i][j]);
    }
}

// stage 64 rows x (4<<lg4) cols from gmem into smem (512-thread version)
template <int NTHR>
__device__ __forceinline__ void stage64(float* dst, int dld, const float* __restrict__ src,
                                        int sld, int lg, int tid)
{
    int n = 64 << lg, m = (1 << lg) - 1;
    for (int i = tid; i < n; i += NTHR) {
        int r = i >> lg, c4 = (i & m) * 4;
        *reinterpret_cast<float4*>(dst + r * dld + c4) =
            *reinterpret_cast<const float4*>(src + r * sld + c4);
    }
}

__device__ __forceinline__ void ln64(const float* src, float* dst,
                                     const float* __restrict__ gg, const float* __restrict__ bb,
                                     int warp, int lane)
{
#pragma unroll 1
    for (int q = 0; q < 8; q++) {
        int s = warp * 8 + q;
        float v0 = src[s * PL + lane], v1 = src[s * PL + lane + 32];
        float s1 = v0 + v1, s2 = v0 * v0 + v1 * v1;
#pragma unroll
        for (int o = 16; o > 0; o >>= 1) {
            s1 += __shfl_xor_sync(~0u, s1, o);
            s2 += __shfl_xor_sync(~0u, s2, o);
        }
        float m = s1 * (1.0f / 64.0f);
        float r = rsqrtf(fmaxf(s2 * (1.0f / 64.0f) - m * m, 0.0f) + 1e-5f);
        dst[s * PL + lane]      = (v0 - m) * r * gg[lane] + bb[lane];
        dst[s * PL + lane + 32] = (v1 - m) * r * gg[lane + 32] + bb[lane + 32];
    }
}

// ============================ K1: phase 1 (512 threads) ============================
extern "C" __global__ void __launch_bounds__(512, 1)
k1(const float* __restrict__ xg, const float* __restrict__ geo,
   const float* __restrict__ g1, const float* __restrict__ b1,
   const float* __restrict__ Wsh, const float* __restrict__ bsh,
   const float* __restrict__ Wfe, const float* __restrict__ bfe,
   const float* __restrict__ Wasn, const float* __restrict__ basn)
{
    extern __shared__ float sm[];
    float* sA   = sm;                 // 64 x PC  (hn, then feat)
    float* sP   = sA + 64 * PC;       // 64 x 256 slice partial
    float* sSh  = sP + 64 * 256;      // 64 x PL
    float* sLg  = sSh + 64 * PL;      // 64 x PL
    float* sGeo = sLg + 64 * PL;      // 64 x PL
    float* sW   = sGeo + 64 * PL;     // 64 x PL weight stage
    float* sG1  = sW + 64 * PL;       // 256
    float* sB1  = sG1 + 256;
    float* sBfe = sB1 + 256;
    float* sBsh = sBfe + 256;         // 64
    float* sBa  = sBsh + 64;          // 64

    const int tid = threadIdx.x;
    const int tr = tid >> 4, tc = tid & 15;       // tr 0..31, tc 0..15
    const int warp = tid >> 5, lane = tid & 31;   // 16 warps
    const int b = blockIdx.x / BPB, rb = blockIdx.x % BPB;

    for (int i = tid; i < 64 * 256; i += 512) sP[i] = 0.0f;
    if (tid < 256) { sG1[tid] = g1[tid]; sB1[tid] = b1[tid]; sBfe[tid] = bfe[tid]; }
    if (tid < 64) { sBsh[tid] = bsh[tid]; sBa[tid] = basn[tid]; }
    float wloc = 0.0f;
    __syncthreads();

    for (int tile = rb; tile < NTILE; tile += BPB) {
        const size_t tok0 = (size_t)b * NTOK + (size_t)tile * TT;
        __syncthreads();   // protect sA/sLg from previous iteration's readers

        // LN1 -> sA; geo -> sGeo   (16 warps x 4 rows each)
#pragma unroll 1
        for (int q = 0; q < 4; q++) {
            int t = warp * 4 + q;
            const float* row = xg + (tok0 + t) * CD;
            float v[8], s1 = 0.0f, s2 = 0.0f;
#pragma unroll
            for (int k = 0; k < 8; k++) { v[k] = row[lane + 32 * k]; s1 += v[k]; s2 += v[k] * v[k]; }
#pragma unroll
            for (int o = 16; o > 0; o >>= 1) {
                s1 += __shfl_xor_sync(~0u, s1, o);
                s2 += __shfl_xor_sync(~0u, s2, o);
            }
            float m = s1 * (1.0f / 256.0f);
            float r = rsqrtf(fmaxf(s2 * (1.0f / 256.0f) - m * m, 0.0f) + 1e-5f);
#pragma unroll
            for (int k = 0; k < 8; k++) {
                int c = lane + 32 * k;
                sA[t * PC + c] = (v[k] - m) * r * sG1[c] + sB1[c];
            }
        }
        for (int i = tid; i < 64 * 64; i += 512) {
            int t = i >> 6, s = i & 63;
            sGeo[t * PL + s] = geo[(tok0 + t) * LD + s];
        }
        __syncthreads();

        // GEMM1: shared = hn @ Wsh  (K=256)
        float a1[2][4] = {};
        for (int kt = 0; kt < 4; kt++) {
            __syncthreads();
            stage64<512>(sW, PL, Wsh + kt * 64 * 64, 64, 4, tid);
            __syncthreads();
            mm2x4(sA + kt * 64, PC, sW, PL, tr, tc, a1);
        }
#pragma unroll
        for (int i = 0; i < 2; i++)
#pragma unroll
            for (int j = 0; j < 4; j++)
                sSh[(tr + 32 * i) * PL + tc * 4 + j] = a1[i][j] + sBsh[tc * 4 + j];

        // GEMM2: feat = shared @ Wfe  (K=64), overwrite sA
        for (int cc = 0; cc < 4; cc++) {
            __syncthreads();
            stage64<512>(sW, PL, Wfe + cc * 64, 256, 4, tid);
            __syncthreads();
            float a2[2][4] = {};
            mm2x4(sSh, PL, sW, PL, tr, tc, a2);
#pragma unroll
            for (int i = 0; i < 2; i++)
#pragma unroll
                for (int j = 0; j < 4; j++) {
                    int c = cc * 64 + tc * 4 + j;
                    sA[(tr + 32 * i) * PC + c] = a2[i][j] + sBfe[c];
                }
        }

        // GEMM3: logits = [shared|geo] @ Wasn  (K=128)
        float a3[2][4] = {};
        __syncthreads();
        stage64<512>(sW, PL, Wasn, 64, 4, tid);
        __syncthreads();
        mm2x4(sSh, PL, sW, PL, tr, tc, a3);
        __syncthreads();
        stage64<512>(sW, PL, Wasn + 64 * 64, 64, 4, tid);
        __syncthreads();
        mm2x4(sGeo, PL, sW, PL, tr, tc, a3);
#pragma unroll
        for (int i = 0; i < 2; i++)
#pragma unroll
            for (int j = 0; j < 4; j++)
                sLg[(tr + 32 * i) * PL + tc * 4 + j] = a3[i][j] + sBa[tc * 4 + j];
        __syncthreads();

        // softmax rows -> w (smem + gmem spill)
#pragma unroll 1
        for (int q = 0; q < 4; q++) {
            int t = warp * 4 + q;
            float v0 = sLg[t * PL + lane], v1 = sLg[t * PL + lane + 32];
            float mx = fmaxf(v0, v1);
#pragma unroll
            for (int o = 16; o > 0; o >>= 1) mx = fmaxf(mx, __shfl_xor_sync(~0u, mx, o));
            float e0 = __expf(v0 - mx), e1 = __expf(v1 - mx), ss = e0 + e1;
#pragma unroll
            for (int o = 16; o > 0; o >>= 1) ss += __shfl_xor_sync(~0u, ss, o);
            float inv = 1.0f / ss;
            float w0 = e0 * inv, w1 = e1 * inv;
            sLg[t * PL + lane] = w0; sLg[t * PL + lane + 32] = w1;
            float* wo = g_w + (tok0 + t) * SD;
            wo[lane] = w0; wo[lane + 32] = w1;
        }
        __syncthreads();

        if (tid < 64) {
            float cs = 0.0f;
            for (int t = 0; t < 64; t++) cs += sLg[t * PL + tid];
            wloc += cs;
        }

        // GEMM4: sP += w^T @ feat
        for (int cc = 0; cc < 4; cc++) {
            float a4[2][4] = {};
            mmT2x4(sLg, PL, sA + cc * 64, PC, tr, tc, a4);
#pragma unroll
            for (int i = 0; i < 2; i++)
#pragma unroll
                for (int j = 0; j < 4; j++)
                    sP[(tr + 32 * i) * 256 + cc * 64 + tc * 4 + j] += a4[i][j];
        }
    }

    __syncthreads();
    if (tid < 64) atomicAdd(&g_wsum[b * 64 + tid], wloc);
    for (int i = tid; i < 64 * 256; i += 512) atomicAdd(&g_slice[b * 16384 + i], sP[i]);
}

// ============================ K2: latent transition (256 threads, tiny) ============================
extern "C" __global__ void __launch_bounds__(256, 1)
k2(const float* __restrict__ Wd, const float* __restrict__ bd,
   const float* __restrict__ gdn, const float* __restrict__ bdn,
   const float* __restrict__ Wanc, const float* __restrict__ banc,
   const float* __restrict__ Wself, const float* __restrict__ Wctx,
   const float* __restrict__ gon, const float* __restrict__ bon,
   const float* __restrict__ Wup, const float* __restrict__ bup)
{
    extern __shared__ float sm[];
    float* sS  = sm;               // 64 x PC
    float* sWb = sS + 64 * PC;     // 256 x PL
    float* sT1 = sWb + 256 * PL;   // 64 x PL (ls)
    float* sT2 = sT1 + 64 * PL;    // 64 x PL
    float* sCx = sT2 + 64 * PL;    // 64 x PL
    float* sAn = sCx + 64 * PL;    // 16 x PL
    float* sAw = sAn + 16 * PL;    // 64 x 20
    float* sAs = sAw + 64 * 20;    // 16
    float* sWm = sAs + 16;         // 64

    const int tid = threadIdx.x;
    const int tr = tid >> 4, tc = tid & 15;
    const int warp = tid >> 5, lane = tid & 31;
    const int b = blockIdx.x;

    if (tid < 64) sWm[tid] = fmaxf(g_wsum[b * 64 + tid], 1e-6f);
    __syncthreads();
    for (int i = tid; i < 64 * 256; i += 256) {
        int s = i >> 8;
        sS[s * PC + (i & 255)] = g_slice[b * 16384 + i] / sWm[s];
    }
    for (int i = tid; i < 256 * 16; i += 256) {
        int r = i >> 4, c4 = (i & 15) * 4;
        *reinterpret_cast<float4*>(sWb + r * PL + c4) =
            *reinterpret_cast<const float4*>(Wd + r * 64 + c4);
    }
    __syncthreads();

    {
        float acc[4][4] = {};
        for (int kt = 0; kt < 4; kt++)
            mm64q(sS + kt * 64, PC, sWb + kt * 64 * PL, PL, tr, tc, acc);
#pragma unroll
        for (int i = 0; i < 4; i++)
#pragma unroll
            for (int j = 0; j < 4; j++) {
                int c = tc * 4 + j;
                sT2[(tr + 16 * i) * PL + c] = acc[i][j] + bd[c];
            }
    }
    __syncthreads();
    ln64(sT2, sT1, gdn, bdn, warp, lane);
    __syncthreads();

    {
        int s = tid >> 2, a0 = (tid & 3) * 4;
        float a4[4] = {0.f, 0.f, 0.f, 0.f};
        for (int k = 0; k < 64; k++) {
            float av = sT1[s * PL + k];
#pragma unroll
            for (int j = 0; j < 4; j++) a4[j] = fmaf(av, Wanc[k * 16 + a0 + j], a4[j]);
        }
#pragma unroll
        for (int j = 0; j < 4; j++) sAw[s * 20 + a0 + j] = a4[j] + banc[a0 + j];
    }
    __syncthreads();
    if (tid < 64) {
        float mx = -1e30f;
        for (int a = 0; a < 16; a++) mx = fmaxf(mx, sAw[tid * 20 + a]);
        float e[16], ss = 0.0f;
        for (int a = 0; a < 16; a++) { e[a] = __expf(sAw[tid * 20 + a] - mx); ss += e[a]; }
        float inv = 1.0f / ss;
        for (int a = 0; a < 16; a++) sAw[tid * 20 + a] = e[a] * inv;
    }
    __syncthreads();
    if (tid < 16) {
        float cs = 0.0f;
        for (int s = 0; s < 64; s++) cs += sAw[s * 20 + tid];
        sAs[tid] = fmaxf(cs, 1e-6f);
    }
    __syncthreads();
    for (int idx = tid; idx < 16 * 64; idx += 256) {
        int a = idx >> 6, d = idx & 63;
        float s = 0.0f;
        for (int t = 0; t < 64; t++) s = fmaf(sAw[t * 20 + a], sT1[t * PL + d], s);
        sAn[a * PL + d] = s / sAs[a];
    }
    __syncthreads();
    for (int idx = tid; idx < 64 * 64; idx += 256) {
        int s = idx >> 6, d = idx & 63;
        float v = 0.0f;
#pragma unroll
        for (int a = 0; a < 16; a++) v = fmaf(sAw[s * 20 + a], sAn[a * PL + d], v);
        sCx[s * PL + d] = v;
    }
    __syncthreads();

    {
        float acc[4][4] = {};
        for (int i = tid; i < 64 * 16; i += 256) {
            int r = i >> 4, c4 = (i & 15) * 4;
            *reinterpret_cast<float4*>(sWb + r * PL + c4) =
                *reinterpret_cast<const float4*>(Wself + r * 64 + c4);
        }
        __syncthreads();
        mm64q(sT1, PL, sWb, PL, tr, tc, acc);
        __syncthreads();
        for (int i = tid; i < 64 * 16; i += 256) {
            int r = i >> 4, c4 = (i & 15) * 4;
            *reinterpret_cast<float4*>(sWb + r * PL + c4) =
                *reinterpret_cast<const float4*>(Wctx + r * 64 + c4);
        }
        __syncthreads();
        mm64q(sCx, PL, sWb, PL, tr, tc, acc);
#pragma unroll
        for (int i = 0; i < 4; i++)
#pragma unroll
            for (int j = 0; j < 4; j++) {
                int row = tr + 16 * i, c = tc * 4 + j;
                sT2[row * PL + c] = sT1[row * PL + c] + geluf(acc[i][j]);
            }
    }
    __syncthreads();
    ln64(sT2, sCx, gon, bon, warp, lane);
    __syncthreads();

    for (int cc = 0; cc < 4; cc++) {
        __syncthreads();
        for (int i = tid; i < 64 * 16; i += 256) {
            int r = i >> 4, c4 = (i & 15) * 4;
            *reinterpret_cast<float4*>(sWb + r * PL + c4) =
                *reinterpret_cast<const float4*>(Wup + r * 256 + cc * 64 + c4);
        }
        __syncthreads();
        float acc[4][4] = {};
        mm64q(sCx, PL, sWb, PL, tr, tc, acc);
#pragma unroll
        for (int i = 0; i < 4; i++)
#pragma unroll
            for (int j = 0; j < 4; j++) {
                int row = tr + 16 * i, c = cc * 64 + tc * 4 + j;
                g_st[b * 16384 + row * 256 + c] = acc[i][j] + bup[c];
            }
    }
}

// ============================ K3: reader + channel mixer (512 threads) ============================
extern "C" __global__ void __launch_bounds__(512, 1)
k3(const float* __restrict__ xg,
   const float* __restrict__ g2, const float* __restrict__ b2,
   const float* __restrict__ Win, const float* __restrict__ binp,
   const float* __restrict__ Wout, const float* __restrict__ boutp,
   float* __restrict__ out)
{
    extern __shared__ float sm[];
    float* sSt = sm;               // 64 x PC (st for this batch)
    float* sY  = sSt + 64 * PC;    // 64 x PC (y, then LN(y))
    float* sWt = sY + 64 * PC;     // 64 x PL (w tile)
    float* sWs = sWt + 64 * PL;    // 64 x PV (weight stage)
    float* sVG = sWs + 64 * PV;    // 64 x PL (act)
    float* sG2 = sVG + 64 * PL;    // 256
    float* sB2 = sG2 + 256;        // 256
    float* sBi = sB2 + 256;        // 128

    const int tid = threadIdx.x;
    const int tr = tid >> 4, tc = tid & 15;
    const int warp = tid >> 5, lane = tid & 31;
    const int b = blockIdx.x / BPB, rb = blockIdx.x % BPB;

    if (tid < 256) { sG2[tid] = g2[tid]; sB2[tid] = b2[tid]; }
    if (tid < 128) sBi[tid] = binp[tid];
    for (int i = tid; i < 64 * 256; i += 512) {
        int s = i >> 8;
        sSt[s * PC + (i & 255)] = g_st[b * 16384 + i];
    }
    __syncthreads();

    for (int tile = rb; tile < NTILE; tile += BPB) {
        const size_t tok0 = (size_t)b * NTOK + (size_t)tile * TT;
        __syncthreads();
        for (int i = tid; i < 64 * 64; i += 512) {
            int t = i >> 6, s = i & 63;
            sWt[t * PL + s] = g_w[(tok0 + t) * SD + s];
        }
        __syncthreads();

        // y = x + w@st ; write y to out, keep in sY
        for (int cc = 0; cc < 4; cc++) {
            float ay[2][4] = {};
            mm2x4(sWt, PL, sSt + cc * 64, PC, tr, tc, ay);
#pragma unroll
            for (int i = 0; i < 2; i++) {
                int row = tr + 32 * i, c = cc * 64 + tc * 4;
                float4 xv = *reinterpret_cast<const float4*>(xg + (tok0 + row) * CD + c);
                float4 yv = make_float4(ay[i][0] + xv.x, ay[i][1] + xv.y,
                                        ay[i][2] + xv.z, ay[i][3] + xv.w);
                *reinterpret_cast<float4*>(sY + row * PC + c) = yv;
                *reinterpret_cast<float4*>(out + (tok0 + row) * CD + c) = yv;
            }
        }
        __syncthreads();

        // LN2 in place on sY
#pragma unroll 1
        for (int q = 0; q < 4; q++) {
            int t = warp * 4 + q;
            float v[8], s1 = 0.0f, s2 = 0.0f;
#pragma unroll
            for (int k = 0; k < 8; k++) { v[k] = sY[t * PC + lane + 32 * k]; s1 += v[k]; s2 += v[k] * v[k]; }
#pragma unroll
            for (int o = 16; o > 0; o >>= 1) {
                s1 += __shfl_xor_sync(~0u, s1, o);
                s2 += __shfl_xor_sync(~0u, s2, o);
            }
            float m = s1 * (1.0f / 256.0f);
            float r = rsqrtf(fmaxf(s2 * (1.0f / 256.0f) - m * m, 0.0f) + 1e-5f);
#pragma unroll
            for (int k = 0; k < 8; k++) {
                int c = lane + 32 * k;
                sY[t * PC + c] = (v[k] - m) * r * sG2[c] + sB2[c];
            }
        }

        // vg = h @ Win (256 -> 128), both 64-col chunks in registers
        float av[2][2][4] = {};
        for (int kt = 0; kt < 4; kt++) {
            __syncthreads();
            stage64<512>(sWs, PV, Win + kt * 64 * 128, 128, 5, tid);
            __syncthreads();
            mm2x4(sY + kt * 64, PC, sWs, PV, tr, tc, av[0]);
            mm2x4(sY + kt * 64, PC, sWs + 64, PV, tr, tc, av[1]);
        }
#pragma unroll
        for (int i = 0; i < 2; i++)
#pragma unroll
            for (int j = 0; j < 4; j++) {
                int c = tc * 4 + j;
                float v = av[0][i][j] + sBi[c];
                float gg = av[1][i][j] + sBi[64 + c];
                sVG[(tr + 32 * i) * PL + c] = geluf(v) * (1.0f / (1.0f + __expf(-gg)));
            }

        // out = y + act @ Wout + bout
        for (int cc = 0; cc < 4; cc++) {
            __syncthreads();
            stage64<512>(sWs, PV, Wout + cc * 64, 256, 4, tid);
            __syncthreads();
            float ao[2][4] = {};
            mm2x4(sVG, PL, sWs, PV, tr, tc, ao);
#pragma unroll
            for (int i = 0; i < 2; i++) {
                int row = tr + 32 * i, c = cc * 64 + tc * 4;
                float4 yv = *reinterpret_cast<const float4*>(out + (tok0 + row) * CD + c);
                float4 bo = *reinterpret_cast<const float4*>(boutp + c);
                float4 ov = make_float4(yv.x + ao[i][0] + bo.x, yv.y + ao[i][1] + bo.y,
                                        yv.z + ao[i][2] + bo.z, yv.w + ao[i][3] + bo.w);
                *reinterpret_cast<float4*>(out + (tok0 + row) * CD + c) = ov;
            }
        }
    }
}

// ============================ launcher ============================
extern "C" void kernel_launch(void* const* d_in, const int* in_sizes, int n_in,
                              void* d_out, int out_size)
{
    const float* x     = (const float*)d_in[0];
    const float* geo   = (const float*)d_in[1];
    const float* ln1g  = (const float*)d_in[2];
    const float* ln1b  = (const float*)d_in[3];
    const float* Wsh   = (const float*)d_in[4];
    const float* bsh   = (const float*)d_in[5];
    const float* Wfe   = (const float*)d_in[6];
    const float* bfe   = (const float*)d_in[7];
    const float* Wasn  = (const float*)d_in[8];
    const float* basn  = (const float*)d_in[9];
    const float* Wd    = (const float*)d_in[10];
    const float* bd    = (const float*)d_in[11];
    const float* gdn   = (const float*)d_in[12];
    const float* bdn   = (const float*)d_in[13];
    const float* Wanc  = (const float*)d_in[14];
    const float* banc  = (const float*)d_in[15];
    const float* Wself = (const float*)d_in[16];
    const float* Wctx  = (const float*)d_in[17];
    const float* gon   = (const float*)d_in[18];
    const float* bon   = (const float*)d_in[19];
    const float* Wup   = (const float*)d_in[20];
    const float* bup   = (const float*)d_in[21];
    const float* ln2g  = (const float*)d_in[22];
    const float* ln2b  = (const float*)d_in[23];
    const float* Win   = (const float*)d_in[24];
    const float* binp  = (const float*)d_in[25];
    const float* Wout  = (const float*)d_in[26];
    const float* boutp = (const float*)d_in[27];
    float* out = (float*)d_out;

    const size_t S1 = (size_t)(64 * PC + 64 * 256 + 4 * 64 * PL + 3 * 256 + 2 * 64) * sizeof(float);
    const size_t S2 = (size_t)(64 * PC + 256 * PL + 3 * 64 * PL + 16 * PL + 64 * 20 + 16 + 64) * sizeof(float);
    const size_t S3 = (size_t)(2 * 64 * PC + 64 * PL + 64 * PV + 64 * PL + 256 + 256 + 128) * sizeof(float);

    cudaFuncSetAttribute(k1, cudaFuncAttributeMaxDynamicSharedMemorySize, (int)S1);
    cudaFuncSetAttribute(k2, cudaFuncAttributeMaxDynamicSharedMemorySize, (int)S2);
    cudaFuncSetAttribute(k3, cudaFuncAttributeMaxDynamicSharedMemorySize, (int)S3);

    void* pslice = nullptr; void* pwsum = nullptr;
    cudaGetSymbolAddress(&pslice, g_slice);
    cudaGetSymbolAddress(&pwsum, g_wsum);
    cudaMemsetAsync(pslice, 0, (size_t)NB * SD * CD * sizeof(float), 0);
    cudaMemsetAsync(pwsum, 0, (size_t)NB * SD * sizeof(float), 0);

    k1<<<NB * BPB, 512, S1>>>(x, geo, ln1g, ln1b, Wsh, bsh, Wfe, bfe, Wasn, basn);
    k2<<<NB, 256, S2>>>(Wd, bd, gdn, bdn, Wanc, banc, Wself, Wctx, gon, bon, Wup, bup);
    k3<<<NB * BPB, 512, S3>>>(x, ln2g, ln2b, Win, binp, Wout, boutp, out);
}

// round 6
// speedup vs baseline: 1.4511x; 1.4511x over previous
#include <cuda_runtime.h>
#include <math.h>

#define NB   4
#define NTOK 65536
#define CD   256
#define LD   64
#define SD   64
#define AD   16
#define TT   64
#define BPB  37
#define NTILE 1024
#define PC 260
#define PL 68
#define PV 132

__device__ float g_w[(size_t)NB * NTOK * SD];   // softmax assignment weights
__device__ float g_M[NB * SD * LD];             // accumulated w^T @ shared
__device__ float g_wsum[NB * SD];
__device__ float g_st[NB * SD * CD];

__device__ __forceinline__ float geluf(float x) {
    return 0.5f * x * (1.0f + erff(x * 0.70710678118654752f));
}

// C[64x64] += A[64x64](ld ald) @ B[64x64](ld bld); thread (tr,tc) owns rows tr+16i, cols tc*4+j
__device__ __forceinline__ void mm64(const float* __restrict__ A, int ald,
                                     const float* __restrict__ B, int bld,
                                     int tr, int tc, float (&acc)[4][4])
{
#pragma unroll 8
    for (int kk = 0; kk < 64; kk++) {
        float4 b4 = *reinterpret_cast<const float4*>(B + kk * bld + tc * 4);
        float a[4] = { A[tr * ald + kk], A[(tr + 16) * ald + kk],
                       A[(tr + 32) * ald + kk], A[(tr + 48) * ald + kk] };
        float bb[4] = { b4.x, b4.y, b4.z, b4.w };
#pragma unroll
        for (int i = 0; i < 4; i++)
#pragma unroll
            for (int j = 0; j < 4; j++) acc[i][j] = fmaf(a[i], bb[j], acc[i][j]);
    }
}

// Same, A transposed: A[k][row] with ld ald
__device__ __forceinline__ void mmT64(const float* __restrict__ A, int ald,
                                      const float* __restrict__ B, int bld,
                                      int tr, int tc, float (&acc)[4][4])
{
#pragma unroll 8
    for (int kk = 0; kk < 64; kk++) {
        float4 b4 = *reinterpret_cast<const float4*>(B + kk * bld + tc * 4);
        float a[4] = { A[kk * ald + tr], A[kk * ald + tr + 16],
                       A[kk * ald + tr + 32], A[kk * ald + tr + 48] };
        float bb[4] = { b4.x, b4.y, b4.z, b4.w };
#pragma unroll
        for (int i = 0; i < 4; i++)
#pragma unroll
            for (int j = 0; j < 4; j++) acc[i][j] = fmaf(a[i], bb[j], acc[i][j]);
    }
}

// stage 64 rows x (16<<(lg-4)) float4 cols from gmem into smem
__device__ __forceinline__ void stage64(float* dst, int dld, const float* __restrict__ src,
                                        int sld, int lg, int tid)
{
    int n = 64 << lg, m = (1 << lg) - 1;
    for (int i = tid; i < n; i += 256) {
        int r = i >> lg, c4 = (i & m) * 4;
        *reinterpret_cast<float4*>(dst + r * dld + c4) =
            *reinterpret_cast<const float4*>(src + r * sld + c4);
    }
}

// LN over rows of length 64, pitch PL
__device__ __forceinline__ void ln64(const float* src, float* dst,
                                     const float* __restrict__ gg, const float* __restrict__ bb,
                                     int warp, int lane)
{
#pragma unroll 1
    for (int q = 0; q < 8; q++) {
        int s = warp * 8 + q;
        float v0 = src[s * PL + lane], v1 = src[s * PL + lane + 32];
        float s1 = v0 + v1, s2 = v0 * v0 + v1 * v1;
#pragma unroll
        for (int o = 16; o > 0; o >>= 1) {
            s1 += __shfl_xor_sync(~0u, s1, o);
            s2 += __shfl_xor_sync(~0u, s2, o);
        }
        float m = s1 * (1.0f / 64.0f);
        float r = rsqrtf(fmaxf(s2 * (1.0f / 64.0f) - m * m, 0.0f) + 1e-5f);
        dst[s * PL + lane]      = (v0 - m) * r * gg[lane] + bb[lane];
        dst[s * PL + lane + 32] = (v1 - m) * r * gg[lane + 32] + bb[lane + 32];
    }
}

// ============================ K1: phase 1 (fused, no feat GEMM) ============================
extern "C" __global__ void __launch_bounds__(256, 1)
k1(const float* __restrict__ xg, const float* __restrict__ geo,
   const float* __restrict__ g1, const float* __restrict__ b1,
   const float* __restrict__ Wsh, const float* __restrict__ bsh,
   const float* __restrict__ Wasn, const float* __restrict__ basn)
{
    extern __shared__ float sm[];
    float* sA   = sm;                 // 64 x PC  (hn)
    float* sSh  = sA + 64 * PC;       // 64 x PL  (shared)
    float* sLg  = sSh + 64 * PL;      // 64 x PL  (logits -> w)
    float* sGeo = sLg + 64 * PL;      // 64 x PL
    float* sW   = sGeo + 64 * PL;     // 64 x PL  weight stage
    float* sG1  = sW + 64 * PL;       // 256
    float* sB1  = sG1 + 256;          // 256
    float* sBsh = sB1 + 256;          // 64
    float* sBa  = sBsh + 64;          // 64

    const int tid = threadIdx.x;
    const int tr = tid >> 4, tc = tid & 15;
    const int warp = tid >> 5, lane = tid & 31;
    const int b = blockIdx.x / BPB, rb = blockIdx.x % BPB;

    sG1[tid] = g1[tid]; sB1[tid] = b1[tid];
    if (tid < 64) { sBsh[tid] = bsh[tid]; sBa[tid] = basn[tid]; }
    float wloc = 0.0f;
    float Macc[4][4] = {};   // persistent w^T @ shared accumulator (registers)
    __syncthreads();

    for (int tile = rb; tile < NTILE; tile += BPB) {
        const size_t tok0 = (size_t)b * NTOK + (size_t)tile * TT;
        __syncthreads();   // previous iteration's readers of sA/sGeo/sSh/sLg done

        // LN1 -> sA; geo -> sGeo
#pragma unroll 1
        for (int q = 0; q < 8; q++) {
            int t = warp * 8 + q;
            const float* row = xg + (tok0 + t) * CD;
            float v[8], s1 = 0.0f, s2 = 0.0f;
#pragma unroll
            for (int k = 0; k < 8; k++) { v[k] = row[lane + 32 * k]; s1 += v[k]; s2 += v[k] * v[k]; }
#pragma unroll
            for (int o = 16; o > 0; o >>= 1) {
                s1 += __shfl_xor_sync(~0u, s1, o);
                s2 += __shfl_xor_sync(~0u, s2, o);
            }
            float m = s1 * (1.0f / 256.0f);
            float r = rsqrtf(fmaxf(s2 * (1.0f / 256.0f) - m * m, 0.0f) + 1e-5f);
#pragma unroll
            for (int k = 0; k < 8; k++) {
                int c = lane + 32 * k;
                sA[t * PC + c] = (v[k] - m) * r * sG1[c] + sB1[c];
            }
        }
        for (int i = tid; i < 64 * 64; i += 256) {
            int t = i >> 6, s = i & 63;
            sGeo[t * PL + s] = geo[(tok0 + t) * LD + s];
        }
        __syncthreads();

        // GEMM1: shared = hn @ Wsh  (K=256)
        float a1[4][4] = {};
        for (int kt = 0; kt < 4; kt++) {
            __syncthreads();
            stage64(sW, PL, Wsh + kt * 64 * 64, 64, 4, tid);
            __syncthreads();
            mm64(sA + kt * 64, PC, sW, PL, tr, tc, a1);
        }
#pragma unroll
        for (int i = 0; i < 4; i++)
#pragma unroll
            for (int j = 0; j < 4; j++)
                sSh[(tr + 16 * i) * PL + tc * 4 + j] = a1[i][j] + sBsh[tc * 4 + j];

        // GEMM3: logits = [shared|geo] @ Wasn  (K=128)
        float a3[4][4] = {};
        __syncthreads();    // sSh visible + sW reusable
        stage64(sW, PL, Wasn, 64, 4, tid);
        __syncthreads();
        mm64(sSh, PL, sW, PL, tr, tc, a3);
        __syncthreads();
        stage64(sW, PL, Wasn + 64 * 64, 64, 4, tid);
        __syncthreads();
        mm64(sGeo, PL, sW, PL, tr, tc, a3);
#pragma unroll
        for (int i = 0; i < 4; i++)
#pragma unroll
            for (int j = 0; j < 4; j++)
                sLg[(tr + 16 * i) * PL + tc * 4 + j] = a3[i][j] + sBa[tc * 4 + j];
        __syncthreads();

        // softmax rows -> w (smem + gmem spill)
#pragma unroll 1
        for (int q = 0; q < 8; q++) {
            int t = warp * 8 + q;
            float v0 = sLg[t * PL + lane], v1 = sLg[t * PL + lane + 32];
            float mx = fmaxf(v0, v1);
#pragma unroll
            for (int o = 16; o > 0; o >>= 1) mx = fmaxf(mx, __shfl_xor_sync(~0u, mx, o));
            float e0 = __expf(v0 - mx), e1 = __expf(v1 - mx), ss = e0 + e1;
#pragma unroll
            for (int o = 16; o > 0; o >>= 1) ss += __shfl_xor_sync(~0u, ss, o);
            float inv = 1.0f / ss;
            float w0 = e0 * inv, w1 = e1 * inv;
            sLg[t * PL + lane] = w0; sLg[t * PL + lane + 32] = w1;
            float* wo = g_w + (tok0 + t) * SD;
            wo[lane] = w0; wo[lane + 32] = w1;
        }
        __syncthreads();

        if (tid < 64) {
            float cs = 0.0f;
            for (int t = 0; t < 64; t++) cs += sLg[t * PL + tid];
            wloc += cs;
        }

        // GEMM4': Macc += w^T @ shared  (K=64 tokens) — register resident
        mmT64(sLg, PL, sSh, PL, tr, tc, Macc);
    }

    if (tid < 64) atomicAdd(&g_wsum[b * 64 + tid], wloc);
#pragma unroll
    for (int i = 0; i < 4; i++)
#pragma unroll
        for (int j = 0; j < 4; j++)
            atomicAdd(&g_M[b * 4096 + (tr + 16 * i) * 64 + tc * 4 + j], Macc[i][j]);
}

// ============================ K2: slice reconstruction + latent transition ============================
extern "C" __global__ void __launch_bounds__(256, 1)
k2(const float* __restrict__ Wfe, const float* __restrict__ bfe,
   const float* __restrict__ Wd, const float* __restrict__ bd,
   const float* __restrict__ gdn, const float* __restrict__ bdn,
   const float* __restrict__ Wanc, const float* __restrict__ banc,
   const float* __restrict__ Wself, const float* __restrict__ Wctx,
   const float* __restrict__ gon, const float* __restrict__ bon,
   const float* __restrict__ Wup, const float* __restrict__ bup)
{
    extern __shared__ float sm[];
    float* sS  = sm;               // 64 x PC   (slice tokens)
    float* sWb = sS + 64 * PC;     // 256 x PL  (weight staging)
    float* sT1 = sWb + 256 * PL;   // 64 x PL (M staging, then ls)
    float* sT2 = sT1 + 64 * PL;    // 64 x PL
    float* sCx = sT2 + 64 * PL;    // 64 x PL
    float* sAn = sCx + 64 * PL;    // 16 x PL
    float* sAw = sAn + 16 * PL;    // 64 x 20
    float* sAs = sAw + 64 * 20;    // 16
    float* sWm = sAs + 16;         // 64

    const int tid = threadIdx.x;
    const int tr = tid >> 4, tc = tid & 15;
    const int warp = tid >> 5, lane = tid & 31;
    const int b = blockIdx.x;

    if (tid < 64) sWm[tid] = fmaxf(g_wsum[b * 64 + tid], 1e-6f);
    // stage M (w^T@shared accumulator) into sT1
    for (int i = tid; i < 64 * 64; i += 256) {
        int s = i >> 6, l = i & 63;
        sT1[s * PL + l] = g_M[b * 4096 + i];
    }
    __syncthreads();

    // slice = (M @ Wfe + wsum*bfe) / clamp(wsum)
    for (int cc = 0; cc < 4; cc++) {
        __syncthreads();
        stage64(sWb, PL, Wfe + cc * 64, 256, 4, tid);
        __syncthreads();
        float acc[4][4] = {};
        mm64(sT1, PL, sWb, PL, tr, tc, acc);
#pragma unroll
        for (int i = 0; i < 4; i++)
#pragma unroll
            for (int j = 0; j < 4; j++) {
                int s = tr + 16 * i, c = cc * 64 + tc * 4 + j;
                float ws = sWm[s];
                sS[s * PC + c] = (acc[i][j] + ws * bfe[c]) / ws;
            }
    }
    __syncthreads();

    // ld = slice @ Wd + bd
    for (int i = tid; i < 256 * 16; i += 256) {
        int r = i >> 4, c4 = (i & 15) * 4;
        *reinterpret_cast<float4*>(sWb + r * PL + c4) =
            *reinterpret_cast<const float4*>(Wd + r * 64 + c4);
    }
    __syncthreads();
    {
        float acc[4][4] = {};
        for (int kt = 0; kt < 4; kt++)
            mm64(sS + kt * 64, PC, sWb + kt * 64 * PL, PL, tr, tc, acc);
        __syncthreads();
#pragma unroll
        for (int i = 0; i < 4; i++)
#pragma unroll
            for (int j = 0; j < 4; j++) {
                int c = tc * 4 + j;
                sT2[(tr + 16 * i) * PL + c] = acc[i][j] + bd[c];
            }
    }
    __syncthreads();
    ln64(sT2, sT1, gdn, bdn, warp, lane);   // ls -> sT1
    __syncthreads();

    {
        int s = tid >> 2, a0 = (tid & 3) * 4;
        float a4[4] = {0.f, 0.f, 0.f, 0.f};
        for (int k = 0; k < 64; k++) {
            float av = sT1[s * PL + k];
#pragma unroll
            for (int j = 0; j < 4; j++) a4[j] = fmaf(av, Wanc[k * 16 + a0 + j], a4[j]);
        }
#pragma unroll
        for (int j = 0; j < 4; j++) sAw[s * 20 + a0 + j] = a4[j] + banc[a0 + j];
    }
    __syncthreads();
    if (tid < 64) {
        float mx = -1e30f;
        for (int a = 0; a < 16; a++) mx = fmaxf(mx, sAw[tid * 20 + a]);
        float e[16], ss = 0.0f;
        for (int a = 0; a < 16; a++) { e[a] = __expf(sAw[tid * 20 + a] - mx); ss += e[a]; }
        float inv = 1.0f / ss;
        for (int a = 0; a < 16; a++) sAw[tid * 20 + a] = e[a] * inv;
    }
    __syncthreads();
    if (tid < 16) {
        float cs = 0.0f;
        for (int s = 0; s < 64; s++) cs += sAw[s * 20 + tid];
        sAs[tid] = fmaxf(cs, 1e-6f);
    }
    __syncthreads();
    for (int idx = tid; idx < 16 * 64; idx += 256) {
        int a = idx >> 6, d = idx & 63;
        float s = 0.0f;
        for (int t = 0; t < 64; t++) s = fmaf(sAw[t * 20 + a], sT1[t * PL + d], s);
        sAn[a * PL + d] = s / sAs[a];
    }
    __syncthreads();
    for (int idx = tid; idx < 64 * 64; idx += 256) {
        int s = idx >> 6, d = idx & 63;
        float v = 0.0f;
#pragma unroll
        for (int a = 0; a < 16; a++) v = fmaf(sAw[s * 20 + a], sAn[a * PL + d], v);
        sCx[s * PL + d] = v;
    }
    __syncthreads();

    {
        float acc[4][4] = {};
        for (int i = tid; i < 64 * 16; i += 256) {
            int r = i >> 4, c4 = (i & 15) * 4;
            *reinterpret_cast<float4*>(sWb + r * PL + c4) =
                *reinterpret_cast<const float4*>(Wself + r * 64 + c4);
        }
        __syncthreads();
        mm64(sT1, PL, sWb, PL, tr, tc, acc);
        __syncthreads();
        for (int i = tid; i < 64 * 16; i += 256) {
            int r = i >> 4, c4 = (i & 15) * 4;
            *reinterpret_cast<float4*>(sWb + r * PL + c4) =
                *reinterpret_cast<const float4*>(Wctx + r * 64 + c4);
        }
        __syncthreads();
        mm64(sCx, PL, sWb, PL, tr, tc, acc);
#pragma unroll
        for (int i = 0; i < 4; i++)
#pragma unroll
            for (int j = 0; j < 4; j++) {
                int row = tr + 16 * i, c = tc * 4 + j;
                sT2[row * PL + c] = sT1[row * PL + c] + geluf(acc[i][j]);
            }
    }
    __syncthreads();
    ln64(sT2, sCx, gon, bon, warp, lane);
    __syncthreads();

    for (int cc = 0; cc < 4; cc++) {
        __syncthreads();
        for (int i = tid; i < 64 * 16; i += 256) {
            int r = i >> 4, c4 = (i & 15) * 4;
            *reinterpret_cast<float4*>(sWb + r * PL + c4) =
                *reinterpret_cast<const float4*>(Wup + r * 256 + cc * 64 + c4);
        }
        __syncthreads();
        float acc[4][4] = {};
        mm64(sCx, PL, sWb, PL, tr, tc, acc);
#pragma unroll
        for (int i = 0; i < 4; i++)
#pragma unroll
            for (int j = 0; j < 4; j++) {
                int row = tr + 16 * i, c = cc * 64 + tc * 4 + j;
                g_st[b * 16384 + row * 256 + c] = acc[i][j] + bup[c];
            }
    }
}

// ============================ K3: reader + channel mixer ============================
extern "C" __global__ void __launch_bounds__(256, 1)
k3(const float* __restrict__ xg,
   const float* __restrict__ g2, const float* __restrict__ b2,
   const float* __restrict__ Win, const float* __restrict__ binp,
   const float* __restrict__ Wout, const float* __restrict__ boutp,
   float* __restrict__ out)
{
    extern __shared__ float sm[];
    float* sSt = sm;               // 64 x PC (st for this batch)
    float* sY  = sSt + 64 * PC;    // 64 x PC (y, then LN(y))
    float* sWt = sY + 64 * PC;     // 64 x PL (w tile)
    float* sWs = sWt + 64 * PL;    // 64 x PV (weight stage)
    float* sVG = sWs + 64 * PV;    // 64 x PL (act)
    float* sG2 = sVG + 64 * PL;    // 256
    float* sB2 = sG2 + 256;        // 256
    float* sBi = sB2 + 256;        // 128

    const int tid = threadIdx.x;
    const int tr = tid >> 4, tc = tid & 15;
    const int warp = tid >> 5, lane = tid & 31;
    const int b = blockIdx.x / BPB, rb = blockIdx.x % BPB;

    sG2[tid] = g2[tid]; sB2[tid] = b2[tid];
    if (tid < 128) sBi[tid] = binp[tid];
    for (int i = tid; i < 64 * 256; i += 256) {
        int s = i >> 8;
        sSt[s * PC + (i & 255)] = g_st[b * 16384 + i];
    }
    __syncthreads();

    for (int tile = rb; tile < NTILE; tile += BPB) {
        const size_t tok0 = (size_t)b * NTOK + (size_t)tile * TT;
        __syncthreads();
        for (int i = tid; i < 64 * 64; i += 256) {
            int t = i >> 6, s = i & 63;
            sWt[t * PL + s] = g_w[(tok0 + t) * SD + s];
        }
        __syncthreads();

        // y = x + w@st ; write y to out, keep in sY
        for (int cc = 0; cc < 4; cc++) {
            float ay[4][4] = {};
            mm64(sWt, PL, sSt + cc * 64, PC, tr, tc, ay);
#pragma unroll
            for (int i = 0; i < 4; i++) {
                int row = tr + 16 * i, c = cc * 64 + tc * 4;
                float4 xv = *reinterpret_cast<const float4*>(xg + (tok0 + row) * CD + c);
                float4 yv = make_float4(ay[i][0] + xv.x, ay[i][1] + xv.y,
                                        ay[i][2] + xv.z, ay[i][3] + xv.w);
                *reinterpret_cast<float4*>(sY + row * PC + c) = yv;
                *reinterpret_cast<float4*>(out + (tok0 + row) * CD + c) = yv;
            }
        }
        __syncthreads();

        // LN2 in place on sY
#pragma unroll 1
        for (int q = 0; q < 8; q++) {
            int t = warp * 8 + q;
            float v[8], s1 = 0.0f, s2 = 0.0f;
#pragma unroll
            for (int k = 0; k < 8; k++) { v[k] = sY[t * PC + lane + 32 * k]; s1 += v[k]; s2 += v[k] * v[k]; }
#pragma unroll
            for (int o = 16; o > 0; o >>= 1) {
                s1 += __shfl_xor_sync(~0u, s1, o);
                s2 += __shfl_xor_sync(~0u, s2, o);
            }
            float m = s1 * (1.0f / 256.0f);
            float r = rsqrtf(fmaxf(s2 * (1.0f / 256.0f) - m * m, 0.0f) + 1e-5f);
#pragma unroll
            for (int k = 0; k < 8; k++) {
                int c = lane + 32 * k;
                sY[t * PC + c] = (v[k] - m) * r * sG2[c] + sB2[c];
            }
        }

        // vg = h @ Win (256 -> 128), both 64-col chunks accumulated in registers
        float av[2][4][4] = {};
        for (int kt = 0; kt < 4; kt++) {
            __syncthreads();
            stage64(sWs, PV, Win + kt * 64 * 128, 128, 5, tid);
            __syncthreads();
            mm64(sY + kt * 64, PC, sWs, PV, tr, tc, av[0]);
            mm64(sY + kt * 64, PC, sWs + 64, PV, tr, tc, av[1]);
        }
        // act = gelu(v) * sigmoid(g)
#pragma unroll
        for (int i = 0; i < 4; i++)
#pragma unroll
            for (int j = 0; j < 4; j++) {
                int c = tc * 4 + j;
                float v = av[0][i][j] + sBi[c];
                float gg = av[1][i][j] + sBi[64 + c];
                float act = geluf(v) * (1.0f / (1.0f + __expf(-gg)));
                sVG[(tr + 16 * i) * PL + c] = act;
            }

        // out = y + act @ Wout + bout
        for (int cc = 0; cc < 4; cc++) {
            __syncthreads();
            stage64(sWs, PV, Wout + cc * 64, 256, 4, tid);
            __syncthreads();
            float ao[4][4] = {};
            mm64(sVG, PL, sWs, PV, tr, tc, ao);
#pragma unroll
            for (int i = 0; i < 4; i++) {
                int row = tr + 16 * i, c = cc * 64 + tc * 4;
                float4 yv = *reinterpret_cast<const float4*>(out + (tok0 + row) * CD + c);
                float4 bo = *reinterpret_cast<const float4*>(boutp + c);
                float4 ov = make_float4(yv.x + ao[i][0] + bo.x, yv.y + ao[i][1] + bo.y,
                                        yv.z + ao[i][2] + bo.z, yv.w + ao[i][3] + bo.w);
                *reinterpret_cast<float4*>(out + (tok0 + row) * CD + c) = ov;
            }
        }
    }
}

// ============================ launcher ============================
extern "C" void kernel_launch(void* const* d_in, const int* in_sizes, int n_in,
                              void* d_out, int out_size)
{
    const float* x     = (const float*)d_in[0];
    const float* geo   = (const float*)d_in[1];
    const float* ln1g  = (const float*)d_in[2];
    const float* ln1b  = (const float*)d_in[3];
    const float* Wsh   = (const float*)d_in[4];
    const float* bsh   = (const float*)d_in[5];
    const float* Wfe   = (const float*)d_in[6];
    const float* bfe   = (const float*)d_in[7];
    const float* Wasn  = (const float*)d_in[8];
    const float* basn  = (const float*)d_in[9];
    const float* Wd    = (const float*)d_in[10];
    const float* bd    = (const float*)d_in[11];
    const float* gdn   = (const float*)d_in[12];
    const float* bdn   = (const float*)d_in[13];
    const float* Wanc  = (const float*)d_in[14];
    const float* banc  = (const float*)d_in[15];
    const float* Wself = (const float*)d_in[16];
    const float* Wctx  = (const float*)d_in[17];
    const float* gon   = (const float*)d_in[18];
    const float* bon   = (const float*)d_in[19];
    const float* Wup   = (const float*)d_in[20];
    const float* bup   = (const float*)d_in[21];
    const float* ln2g  = (const float*)d_in[22];
    const float* ln2b  = (const float*)d_in[23];
    const float* Win   = (const float*)d_in[24];
    const float* binp  = (const float*)d_in[25];
    const float* Wout  = (const float*)d_in[26];
    const float* boutp = (const float*)d_in[27];
    float* out = (float*)d_out;

    const size_t S1 = (size_t)(64 * PC + 4 * 64 * PL + 2 * 256 + 2 * 64) * sizeof(float);
    const size_t S2 = (size_t)(64 * PC + 256 * PL + 3 * 64 * PL + 16 * PL + 64 * 20 + 16 + 64) * sizeof(float);
    const size_t S3 = (size_t)(2 * 64 * PC + 64 * PL + 64 * PV + 64 * PL + 256 + 256 + 128) * sizeof(float);

    cudaFuncSetAttribute(k1, cudaFuncAttributeMaxDynamicSharedMemorySize, (int)S1);
    cudaFuncSetAttribute(k2, cudaFuncAttributeMaxDynamicSharedMemorySize, (int)S2);
    cudaFuncSetAttribute(k3, cudaFuncAttributeMaxDynamicSharedMemorySize, (int)S3);

    void* pM = nullptr; void* pwsum = nullptr;
    cudaGetSymbolAddress(&pM, g_M);
    cudaGetSymbolAddress(&pwsum, g_wsum);
    cudaMemsetAsync(pM, 0, (size_t)NB * SD * LD * sizeof(float), 0);
    cudaMemsetAsync(pwsum, 0, (size_t)NB * SD * sizeof(float), 0);

    k1<<<NB * BPB, 256, S1>>>(x, geo, ln1g, ln1b, Wsh, bsh, Wasn, basn);
    k2<<<NB, 256, S2>>>(Wfe, bfe, Wd, bd, gdn, bdn, Wanc, banc, Wself, Wctx, gon, bon, Wup, bup);
    k3<<<NB * BPB, 256, S3>>>(x, ln2g, ln2b, Win, binp, Wout, boutp, out);
}

// round 7
// speedup vs baseline: 1.7982x; 1.2392x over previous
#include <cuda_runtime.h>
#include <math.h>

#define NB   4
#define NTOK 65536
#define CD   256
#define LD   64
#define SD   64
#define AD   16
#define TT   64
#define BPB  74
#define NTILE 1024
#define PC 260
#define PL 68

__device__ float g_w[(size_t)NB * NTOK * SD];   // softmax assignment weights
__device__ float g_M[NB * SD * LD];             // accumulated w^T @ shared
__device__ float g_wsum[NB * SD];
__device__ float g_st[NB * SD * CD];

__device__ __forceinline__ float geluf(float x) {
    return 0.5f * x * (1.0f + erff(x * 0.70710678118654752f));
}

// C[64x64] += A[64x64](ld ald) @ B[64x64](ld bld); thread (tr,tc) owns rows tr+16i, cols tc*4+j
__device__ __forceinline__ void mm64(const float* __restrict__ A, int ald,
                                     const float* __restrict__ B, int bld,
                                     int tr, int tc, float (&acc)[4][4])
{
#pragma unroll 8
    for (int kk = 0; kk < 64; kk++) {
        float4 b4 = *reinterpret_cast<const float4*>(B + kk * bld + tc * 4);
        float a[4] = { A[tr * ald + kk], A[(tr + 16) * ald + kk],
                       A[(tr + 32) * ald + kk], A[(tr + 48) * ald + kk] };
        float bb[4] = { b4.x, b4.y, b4.z, b4.w };
#pragma unroll
        for (int i = 0; i < 4; i++)
#pragma unroll
            for (int j = 0; j < 4; j++) acc[i][j] = fmaf(a[i], bb[j], acc[i][j]);
    }
}

// Same, A transposed: A[k][row] with ld ald
__device__ __forceinline__ void mmT64(const float* __restrict__ A, int ald,
                                      const float* __restrict__ B, int bld,
                                      int tr, int tc, float (&acc)[4][4])
{
#pragma unroll 8
    for (int kk = 0; kk < 64; kk++) {
        float4 b4 = *reinterpret_cast<const float4*>(B + kk * bld + tc * 4);
        float a[4] = { A[kk * ald + tr], A[kk * ald + tr + 16],
                       A[kk * ald + tr + 32], A[kk * ald + tr + 48] };
        float bb[4] = { b4.x, b4.y, b4.z, b4.w };
#pragma unroll
        for (int i = 0; i < 4; i++)
#pragma unroll
            for (int j = 0; j < 4; j++) acc[i][j] = fmaf(a[i], bb[j], acc[i][j]);
    }
}

// stage 64 rows x 16 float4 cols (64 cols) from gmem into smem pitch PL
__device__ __forceinline__ void stage64c(float* dst, const float* __restrict__ src,
                                         int sld, int tid)
{
    for (int i = tid; i < 1024; i += 256) {
        int r = i >> 4, c4 = (i & 15) * 4;
        *reinterpret_cast<float4*>(dst + r * PL + c4) =
            *reinterpret_cast<const float4*>(src + r * sld + c4);
    }
}

// LN over rows of length 64, pitch PL
__device__ __forceinline__ void ln64(const float* src, float* dst,
                                     const float* __restrict__ gg, const float* __restrict__ bb,
                                     int warp, int lane)
{
#pragma unroll 1
    for (int q = 0; q < 8; q++) {
        int s = warp * 8 + q;
        float v0 = src[s * PL + lane], v1 = src[s * PL + lane + 32];
        float s1 = v0 + v1, s2 = v0 * v0 + v1 * v1;
#pragma unroll
        for (int o = 16; o > 0; o >>= 1) {
            s1 += __shfl_xor_sync(~0u, s1, o);
            s2 += __shfl_xor_sync(~0u, s2, o);
        }
        float m = s1 * (1.0f / 64.0f);
        float r = rsqrtf(fmaxf(s2 * (1.0f / 64.0f) - m * m, 0.0f) + 1e-5f);
        dst[s * PL + lane]      = (v0 - m) * r * gg[lane] + bb[lane];
        dst[s * PL + lane + 32] = (v1 - m) * r * gg[lane + 32] + bb[lane + 32];
    }
}

// ============================ K1: phase 1 (chunked LN, 2 CTAs/SM) ============================
extern "C" __global__ void __launch_bounds__(256, 2)
k1(const float* __restrict__ xg, const float* __restrict__ geo,
   const float* __restrict__ g1, const float* __restrict__ b1,
   const float* __restrict__ Wsh, const float* __restrict__ bsh,
   const float* __restrict__ Wasn, const float* __restrict__ basn)
{
    extern __shared__ float sm[];
    float* sX   = sm;                 // 64 x PL  (normalized x chunk)
    float* sSh  = sX + 64 * PL;       // 64 x PL  (shared)
    float* sLg  = sSh + 64 * PL;      // 64 x PL  (logits -> w)
    float* sGeo = sLg + 64 * PL;      // 64 x PL
    float* sW   = sGeo + 64 * PL;     // 64 x PL  weight stage
    float* sG1  = sW + 64 * PL;       // 256
    float* sB1  = sG1 + 256;          // 256
    float* sMean = sB1 + 256;         // 64
    float* sRstd = sMean + 64;        // 64
    float* sBsh = sRstd + 64;         // 64
    float* sBa  = sBsh + 64;          // 64

    const int tid = threadIdx.x;
    const int tr = tid >> 4, tc = tid & 15;
    const int warp = tid >> 5, lane = tid & 31;
    const int b = blockIdx.x / BPB, rb = blockIdx.x % BPB;

    sG1[tid] = g1[tid]; sB1[tid] = b1[tid];
    if (tid < 64) { sBsh[tid] = bsh[tid]; sBa[tid] = basn[tid]; }
    float wloc = 0.0f;
    float Macc[4][4] = {};   // persistent w^T @ shared accumulator (registers)
    __syncthreads();

    for (int tile = rb; tile < NTILE; tile += BPB) {
        const size_t tok0 = (size_t)b * NTOK + (size_t)tile * TT;

        // pass 1: LN stats per row (no normalized store)
#pragma unroll 1
        for (int q = 0; q < 8; q++) {
            int t = warp * 8 + q;
            const float* row = xg + (tok0 + t) * CD;
            float s1 = 0.0f, s2 = 0.0f;
#pragma unroll
            for (int k = 0; k < 8; k++) { float v = row[lane + 32 * k]; s1 += v; s2 += v * v; }
#pragma unroll
            for (int o = 16; o > 0; o >>= 1) {
                s1 += __shfl_xor_sync(~0u, s1, o);
                s2 += __shfl_xor_sync(~0u, s2, o);
            }
            if (lane == 0) {
                float m = s1 * (1.0f / 256.0f);
                sMean[t] = m;
                sRstd[t] = rsqrtf(fmaxf(s2 * (1.0f / 256.0f) - m * m, 0.0f) + 1e-5f);
            }
        }
        // geo load
        for (int i = tid; i < 64 * 64; i += 256) {
            int t = i >> 6, s = i & 63;
            sGeo[t * PL + s] = geo[(tok0 + t) * LD + s];
        }

        // GEMM1: shared = LN(x) @ Wsh  (K=256, chunked)
        float a1[4][4] = {};
        for (int kt = 0; kt < 4; kt++) {
            __syncthreads();   // kt=0: stats visible & prev-tile readers done; kt>0: prev mm done
            const int base = kt * 64;
#pragma unroll
            for (int ii = 0; ii < 4; ii++) {
                int idx = tid + ii * 256;
                int r = idx >> 4, c4 = (idx & 15) * 4;
                float4 xv = *reinterpret_cast<const float4*>(xg + (tok0 + r) * CD + base + c4);
                float m = sMean[r], rs = sRstd[r];
                float4 o;
                o.x = (xv.x - m) * rs * sG1[base + c4 + 0] + sB1[base + c4 + 0];
                o.y = (xv.y - m) * rs * sG1[base + c4 + 1] + sB1[base + c4 + 1];
                o.z = (xv.z - m) * rs * sG1[base + c4 + 2] + sB1[base + c4 + 2];
                o.w = (xv.w - m) * rs * sG1[base + c4 + 3] + sB1[base + c4 + 3];
                *reinterpret_cast<float4*>(sX + r * PL + c4) = o;
            }
            stage64c(sW, Wsh + base * 64, 64, tid);
            __syncthreads();
            mm64(sX, PL, sW, PL, tr, tc, a1);
        }
        __syncthreads();       // last mm done; sW free; sSh writable
#pragma unroll
        for (int i = 0; i < 4; i++)
#pragma unroll
            for (int j = 0; j < 4; j++)
                sSh[(tr + 16 * i) * PL + tc * 4 + j] = a1[i][j] + sBsh[tc * 4 + j];
        stage64c(sW, Wasn, 64, tid);
        __syncthreads();       // sSh + sW visible

        // GEMM3: logits = [shared|geo] @ Wasn  (K=128)
        float a3[4][4] = {};
        mm64(sSh, PL, sW, PL, tr, tc, a3);
        __syncthreads();
        stage64c(sW, Wasn + 64 * 64, 64, tid);
        __syncthreads();
        mm64(sGeo, PL, sW, PL, tr, tc, a3);
#pragma unroll
        for (int i = 0; i < 4; i++)
#pragma unroll
            for (int j = 0; j < 4; j++)
                sLg[(tr + 16 * i) * PL + tc * 4 + j] = a3[i][j] + sBa[tc * 4 + j];
        __syncthreads();

        // softmax rows -> w (smem + gmem spill)
#pragma unroll 1
        for (int q = 0; q < 8; q++) {
            int t = warp * 8 + q;
            float v0 = sLg[t * PL + lane], v1 = sLg[t * PL + lane + 32];
            float mx = fmaxf(v0, v1);
#pragma unroll
            for (int o = 16; o > 0; o >>= 1) mx = fmaxf(mx, __shfl_xor_sync(~0u, mx, o));
            float e0 = __expf(v0 - mx), e1 = __expf(v1 - mx), ss = e0 + e1;
#pragma unroll
            for (int o = 16; o > 0; o >>= 1) ss += __shfl_xor_sync(~0u, ss, o);
            float inv = 1.0f / ss;
            float w0 = e0 * inv, w1 = e1 * inv;
            sLg[t * PL + lane] = w0; sLg[t * PL + lane + 32] = w1;
            float* wo = g_w + (tok0 + t) * SD;
            wo[lane] = w0; wo[lane + 32] = w1;
        }
        __syncthreads();

        if (tid < 64) {
            float cs = 0.0f;
            for (int t = 0; t < 64; t++) cs += sLg[t * PL + tid];
            wloc += cs;
        }

        // GEMM4': Macc += w^T @ shared  (register resident)
        mmT64(sLg, PL, sSh, PL, tr, tc, Macc);
        __syncthreads();   // all reads of sLg/sSh/sGeo done before next tile overwrites
    }

    if (tid < 64) atomicAdd(&g_wsum[b * 64 + tid], wloc);
#pragma unroll
    for (int i = 0; i < 4; i++)
#pragma unroll
        for (int j = 0; j < 4; j++)
            atomicAdd(&g_M[b * 4096 + (tr + 16 * i) * 64 + tc * 4 + j], Macc[i][j]);
}

// ============================ K2: slice reconstruction + latent transition ============================
extern "C" __global__ void __launch_bounds__(256, 1)
k2(const float* __restrict__ Wfe, const float* __restrict__ bfe,
   const float* __restrict__ Wd, const float* __restrict__ bd,
   const float* __restrict__ gdn, const float* __restrict__ bdn,
   const float* __restrict__ Wanc, const float* __restrict__ banc,
   const float* __restrict__ Wself, const float* __restrict__ Wctx,
   const float* __restrict__ gon, const float* __restrict__ bon,
   const float* __restrict__ Wup, const float* __restrict__ bup)
{
    extern __shared__ float sm[];
    float* sS  = sm;               // 64 x PC   (slice tokens)
    float* sWb = sS + 64 * PC;     // 256 x PL  (weight staging)
    float* sT1 = sWb + 256 * PL;   // 64 x PL (M staging, then ls)
    float* sT2 = sT1 + 64 * PL;    // 64 x PL
    float* sCx = sT2 + 64 * PL;    // 64 x PL
    float* sAn = sCx + 64 * PL;    // 16 x PL
    float* sAw = sAn + 16 * PL;    // 64 x 20
    float* sAs = sAw + 64 * 20;    // 16
    float* sWm = sAs + 16;         // 64

    const int tid = threadIdx.x;
    const int tr = tid >> 4, tc = tid & 15;
    const int warp = tid >> 5, lane = tid & 31;
    const int b = blockIdx.x;

    if (tid < 64) sWm[tid] = fmaxf(g_wsum[b * 64 + tid], 1e-6f);
    for (int i = tid; i < 64 * 64; i += 256) {
        int s = i >> 6, l = i & 63;
        sT1[s * PL + l] = g_M[b * 4096 + i];
    }
    __syncthreads();

    // slice = (M @ Wfe + wsum*bfe) / clamp(wsum)
    for (int cc = 0; cc < 4; cc++) {
        __syncthreads();
        stage64c(sWb, Wfe + cc * 64, 256, tid);
        __syncthreads();
        float acc[4][4] = {};
        mm64(sT1, PL, sWb, PL, tr, tc, acc);
#pragma unroll
        for (int i = 0; i < 4; i++)
#pragma unroll
            for (int j = 0; j < 4; j++) {
                int s = tr + 16 * i, c = cc * 64 + tc * 4 + j;
                float ws = sWm[s];
                sS[s * PC + c] = (acc[i][j] + ws * bfe[c]) / ws;
            }
    }
    __syncthreads();

    // ld = slice @ Wd + bd
    for (int i = tid; i < 256 * 16; i += 256) {
        int r = i >> 4, c4 = (i & 15) * 4;
        *reinterpret_cast<float4*>(sWb + r * PL + c4) =
            *reinterpret_cast<const float4*>(Wd + r * 64 + c4);
    }
    __syncthreads();
    {
        float acc[4][4] = {};
        for (int kt = 0; kt < 4; kt++)
            mm64(sS + kt * 64, PC, sWb + kt * 64 * PL, PL, tr, tc, acc);
        __syncthreads();
#pragma unroll
        for (int i = 0; i < 4; i++)
#pragma unroll
            for (int j = 0; j < 4; j++) {
                int c = tc * 4 + j;
                sT2[(tr + 16 * i) * PL + c] = acc[i][j] + bd[c];
            }
    }
    __syncthreads();
    ln64(sT2, sT1, gdn, bdn, warp, lane);   // ls -> sT1
    __syncthreads();

    {
        int s = tid >> 2, a0 = (tid & 3) * 4;
        float a4[4] = {0.f, 0.f, 0.f, 0.f};
        for (int k = 0; k < 64; k++) {
            float av = sT1[s * PL + k];
#pragma unroll
            for (int j = 0; j < 4; j++) a4[j] = fmaf(av, Wanc[k * 16 + a0 + j], a4[j]);
        }
#pragma unroll
        for (int j = 0; j < 4; j++) sAw[s * 20 + a0 + j] = a4[j] + banc[a0 + j];
    }
    __syncthreads();
    if (tid < 64) {
        float mx = -1e30f;
        for (int a = 0; a < 16; a++) mx = fmaxf(mx, sAw[tid * 20 + a]);
        float e[16], ss = 0.0f;
        for (int a = 0; a < 16; a++) { e[a] = __expf(sAw[tid * 20 + a] - mx); ss += e[a]; }
        float inv = 1.0f / ss;
        for (int a = 0; a < 16; a++) sAw[tid * 20 + a] = e[a] * inv;
    }
    __syncthreads();
    if (tid < 16) {
        float cs = 0.0f;
        for (int s = 0; s < 64; s++) cs += sAw[s * 20 + tid];
        sAs[tid] = fmaxf(cs, 1e-6f);
    }
    __syncthreads();
    for (int idx = tid; idx < 16 * 64; idx += 256) {
        int a = idx >> 6, d = idx & 63;
        float s = 0.0f;
        for (int t = 0; t < 64; t++) s = fmaf(sAw[t * 20 + a], sT1[t * PL + d], s);
        sAn[a * PL + d] = s / sAs[a];
    }
    __syncthreads();
    for (int idx = tid; idx < 64 * 64; idx += 256) {
        int s = idx >> 6, d = idx & 63;
        float v = 0.0f;
#pragma unroll
        for (int a = 0; a < 16; a++) v = fmaf(sAw[s * 20 + a], sAn[a * PL + d], v);
        sCx[s * PL + d] = v;
    }
    __syncthreads();

    {
        float acc[4][4] = {};
        for (int i = tid; i < 64 * 16; i += 256) {
            int r = i >> 4, c4 = (i & 15) * 4;
            *reinterpret_cast<float4*>(sWb + r * PL + c4) =
                *reinterpret_cast<const float4*>(Wself + r * 64 + c4);
        }
        __syncthreads();
        mm64(sT1, PL, sWb, PL, tr, tc, acc);
        __syncthreads();
        for (int i = tid; i < 64 * 16; i += 256) {
            int r = i >> 4, c4 = (i & 15) * 4;
            *reinterpret_cast<float4*>(sWb + r * PL + c4) =
                *reinterpret_cast<const float4*>(Wctx + r * 64 + c4);
        }
        __syncthreads();
        mm64(sCx, PL, sWb, PL, tr, tc, acc);
#pragma unroll
        for (int i = 0; i < 4; i++)
#pragma unroll
            for (int j = 0; j < 4; j++) {
                int row = tr + 16 * i, c = tc * 4 + j;
                sT2[row * PL + c] = sT1[row * PL + c] + geluf(acc[i][j]);
            }
    }
    __syncthreads();
    ln64(sT2, sCx, gon, bon, warp, lane);
    __syncthreads();

    for (int cc = 0; cc < 4; cc++) {
        __syncthreads();
        for (int i = tid; i < 64 * 16; i += 256) {
            int r = i >> 4, c4 = (i & 15) * 4;
            *reinterpret_cast<float4*>(sWb + r * PL + c4) =
                *reinterpret_cast<const float4*>(Wup + r * 256 + cc * 64 + c4);
        }
        __syncthreads();
        float acc[4][4] = {};
        mm64(sCx, PL, sWb, PL, tr, tc, acc);
#pragma unroll
        for (int i = 0; i < 4; i++)
#pragma unroll
            for (int j = 0; j < 4; j++) {
                int row = tr + 16 * i, c = cc * 64 + tc * 4 + j;
                g_st[b * 16384 + row * 256 + c] = acc[i][j] + bup[c];
            }
    }
}

// ============================ K3: reader + channel mixer (2 CTAs/SM) ============================
extern "C" __global__ void __launch_bounds__(256, 2)
k3(const float* __restrict__ xg,
   const float* __restrict__ g2, const float* __restrict__ b2,
   const float* __restrict__ Win, const float* __restrict__ binp,
   const float* __restrict__ Wout, const float* __restrict__ boutp,
   float* __restrict__ out)
{
    extern __shared__ float sm[];
    float* sH  = sm;               // 64 x PC : LN2(y)
    float* sWt = sH + 64 * PC;     // 64 x PL : w tile, later act
    float* sWs = sWt + 64 * PL;    // 64 x PL : stage (st chunks / Win half0 / Wout)
    float* sG2 = sWs + 64 * PL;    // 256
    float* sB2 = sG2 + 256;        // 256
    float* sBi = sB2 + 256;        // 128

    const int tid = threadIdx.x;
    const int tr = tid >> 4, tc = tid & 15;
    const int warp = tid >> 5, lane = tid & 31;
    const int b = blockIdx.x / BPB, rb = blockIdx.x % BPB;

    sG2[tid] = g2[tid]; sB2[tid] = b2[tid];
    if (tid < 128) sBi[tid] = binp[tid];
    __syncthreads();

    for (int tile = rb; tile < NTILE; tile += BPB) {
        const size_t tok0 = (size_t)b * NTOK + (size_t)tile * TT;
        __syncthreads();   // previous tile's readers of sWt/sWs/sH done

        // load w tile -> sWt
        for (int i = tid; i < 64 * 64; i += 256) {
            int t = i >> 6, s = i & 63;
            sWt[t * PL + s] = g_w[(tok0 + t) * SD + s];
        }

        // y = x + w@st : per-cc, st chunk staged into sWs; write y to out only
        for (int cc = 0; cc < 4; cc++) {
            __syncthreads();    // cc=0: sWt written + prev readers done; cc>0: prev mm done
            stage64c(sWs, g_st + b * 16384 + cc * 64, 256, tid);
            __syncthreads();
            float ay[4][4] = {};
            mm64(sWt, PL, sWs, PL, tr, tc, ay);
#pragma unroll
            for (int i = 0; i < 4; i++) {
                int row = tr + 16 * i, c = cc * 64 + tc * 4;
                float4 xv = *reinterpret_cast<const float4*>(xg + (tok0 + row) * CD + c);
                float4 yv = make_float4(ay[i][0] + xv.x, ay[i][1] + xv.y,
                                        ay[i][2] + xv.z, ay[i][3] + xv.w);
                *reinterpret_cast<float4*>(out + (tok0 + row) * CD + c) = yv;
            }
        }
        __syncthreads();   // all y visible (global, block-scope via syncthreads)

        // LN2: read y back from out, write h -> sH
#pragma unroll 1
        for (int q = 0; q < 8; q++) {
            int t = warp * 8 + q;
            const float* yrow = out + (tok0 + t) * CD;
            float v[8], s1 = 0.0f, s2 = 0.0f;
#pragma unroll
            for (int k = 0; k < 8; k++) { v[k] = yrow[lane + 32 * k]; s1 += v[k]; s2 += v[k] * v[k]; }
#pragma unroll
            for (int o = 16; o > 0; o >>= 1) {
                s1 += __shfl_xor_sync(~0u, s1, o);
                s2 += __shfl_xor_sync(~0u, s2, o);
            }
            float m = s1 * (1.0f / 256.0f);
            float r = rsqrtf(fmaxf(s2 * (1.0f / 256.0f) - m * m, 0.0f) + 1e-5f);
#pragma unroll
            for (int k = 0; k < 8; k++) {
                int c = lane + 32 * k;
                sH[t * PC + c] = (v[k] - m) * r * sG2[c] + sB2[c];
            }
        }

        // vg = h @ Win (256 -> 128): halves staged in sWs (v) and sWt (g)
        float av[2][4][4] = {};
        for (int kt = 0; kt < 4; kt++) {
            __syncthreads();   // kt=0: sH visible + sWt (w) reads done; kt>0: prev mms done
            stage64c(sWs, Win + kt * 64 * 128, 128, tid);
            stage64c(sWt, Win + kt * 64 * 128 + 64, 128, tid);
            __syncthreads();
            mm64(sH + kt * 64, PC, sWs, PL, tr, tc, av[0]);
            mm64(sH + kt * 64, PC, sWt, PL, tr, tc, av[1]);
        }
        __syncthreads();   // mms done; sWt free for act

        // act = gelu(v)*sigmoid(g) -> sWt
#pragma unroll
        for (int i = 0; i < 4; i++)
#pragma unroll
            for (int j = 0; j < 4; j++) {
                int c = tc * 4 + j;
                float v = av[0][i][j] + sBi[c];
                float gg = av[1][i][j] + sBi[64 + c];
                sWt[(tr + 16 * i) * PL + c] = geluf(v) * (1.0f / (1.0f + __expf(-gg)));
            }

        // out = y + act @ Wout + bout
        for (int cc = 0; cc < 4; cc++) {
            __syncthreads();   // cc=0: act visible; cc>0: prev mm done with sWs
            stage64c(sWs, Wout + cc * 64, 256, tid);
            __syncthreads();
            float ao[4][4] = {};
            mm64(sWt, PL, sWs, PL, tr, tc, ao);
#pragma unroll
            for (int i = 0; i < 4; i++) {
                int row = tr + 16 * i, c = cc * 64 + tc * 4;
                float4 yv = *reinterpret_cast<const float4*>(out + (tok0 + row) * CD + c);
                float4 bo = *reinterpret_cast<const float4*>(boutp + c);
                float4 ov = make_float4(yv.x + ao[i][0] + bo.x, yv.y + ao[i][1] + bo.y,
                                        yv.z + ao[i][2] + bo.z, yv.w + ao[i][3] + bo.w);
                *reinterpret_cast<float4*>(out + (tok0 + row) * CD + c) = ov;
            }
        }
    }
}

// ============================ launcher ============================
extern "C" void kernel_launch(void* const* d_in, const int* in_sizes, int n_in,
                              void* d_out, int out_size)
{
    const float* x     = (const float*)d_in[0];
    const float* geo   = (const float*)d_in[1];
    const float* ln1g  = (const float*)d_in[2];
    const float* ln1b  = (const float*)d_in[3];
    const float* Wsh   = (const float*)d_in[4];
    const float* bsh   = (const float*)d_in[5];
    const float* Wfe   = (const float*)d_in[6];
    const float* bfe   = (const float*)d_in[7];
    const float* Wasn  = (const float*)d_in[8];
    const float* basn  = (const float*)d_in[9];
    const float* Wd    = (const float*)d_in[10];
    const float* bd    = (const float*)d_in[11];
    const float* gdn   = (const float*)d_in[12];
    const float* bdn   = (const float*)d_in[13];
    const float* Wanc  = (const float*)d_in[14];
    const float* banc  = (const float*)d_in[15];
    const float* Wself = (const float*)d_in[16];
    const float* Wctx  = (const float*)d_in[17];
    const float* gon   = (const float*)d_in[18];
    const float* bon   = (const float*)d_in[19];
    const float* Wup   = (const float*)d_in[20];
    const float* bup   = (const float*)d_in[21];
    const float* ln2g  = (const float*)d_in[22];
    const float* ln2b  = (const float*)d_in[23];
    const float* Win   = (const float*)d_in[24];
    const float* binp  = (const float*)d_in[25];
    const float* Wout  = (const float*)d_in[26];
    const float* boutp = (const float*)d_in[27];
    float* out = (float*)d_out;

    const size_t S1 = (size_t)(5 * 64 * PL + 2 * 256 + 4 * 64) * sizeof(float);
    const size_t S2 = (size_t)(64 * PC + 256 * PL + 3 * 64 * PL + 16 * PL + 64 * 20 + 16 + 64) * sizeof(float);
    const size_t S3 = (size_t)(64 * PC + 2 * 64 * PL + 2 * 256 + 128) * sizeof(float);

    cudaFuncSetAttribute(k1, cudaFuncAttributeMaxDynamicSharedMemorySize, (int)S1);
    cudaFuncSetAttribute(k2, cudaFuncAttributeMaxDynamicSharedMemorySize, (int)S2);
    cudaFuncSetAttribute(k3, cudaFuncAttributeMaxDynamicSharedMemorySize, (int)S3);

    void* pM = nullptr; void* pwsum = nullptr;
    cudaGetSymbolAddress(&pM, g_M);
    cudaGetSymbolAddress(&pwsum, g_wsum);
    cudaMemsetAsync(pM, 0, (size_t)NB * SD * LD * sizeof(float), 0);
    cudaMemsetAsync(pwsum, 0, (size_t)NB * SD * sizeof(float), 0);

    k1<<<NB * BPB, 256, S1>>>(x, geo, ln1g, ln1b, Wsh, bsh, Wasn, basn);
    k2<<<NB, 256, S2>>>(Wfe, bfe, Wd, bd, gdn, bdn, Wanc, banc, Wself, Wctx, gon, bon, Wup, bup);
    k3<<<NB * BPB, 256, S3>>>(x, ln2g, ln2b, Win, binp, Wout, boutp, out);
}